// round 1
// baseline (speedup 1.0000x reference)
#include <cuda_runtime.h>

#define HH 128
#define WW 128
#define BB 4
#define CC 128
#define GG 2
#define CG 64
#define KIN 576   // 9*64
#define FG 64
#define NPIX (BB*HH*WW)   // 65536

// Scratch (static device globals; no runtime allocation)
__device__ float g_off_buf[(size_t)GG * NPIX * 18];        // offsets per group/pixel
__device__ float g_samp_buf[(size_t)GG * NPIX * KIN];      // bilinear-sampled tensor (302MB)

// ---------------------------------------------------------------------------
// Kernel A: 3x3 SAME conv producing 18 offset channels per group.
// One block per (g, b, y) row; 128 threads = 128 pixels; weights in smem.
// ---------------------------------------------------------------------------
__global__ void offset_conv_kernel(const float* __restrict__ x,
                                   const float* __restrict__ off_w,
                                   const float* __restrict__ off_b) {
    __shared__ float sw[9 * CG * 18];   // 10368 floats = 41.5KB
    int bid = blockIdx.x;               // 0 .. GG*BB*HH-1 (1024)
    int g   = bid >> 9;                 // / (BB*HH) = 512
    int rem = bid & 511;
    int b   = rem >> 7;
    int y   = rem & 127;
    int tid = threadIdx.x;              // 128 threads

    const float* wsrc = off_w + (size_t)g * 9 * CG * 18;
    for (int i = tid; i < 9 * CG * 18; i += 128) sw[i] = wsrc[i];
    __syncthreads();

    int px = tid;
    float acc[18];
#pragma unroll
    for (int oc = 0; oc < 18; oc++) acc[oc] = off_b[g * 18 + oc];

    for (int ky = 0; ky < 3; ky++) {
        int yy = y + ky - 1;
        if (yy < 0 || yy >= HH) continue;
        for (int kx = 0; kx < 3; kx++) {
            int xx = px + kx - 1;
            if (xx >= 0 && xx < WW) {
                const float* xp = x + (((size_t)(b * HH + yy) * WW + xx) * CC + g * CG);
                const float* wp = sw + (ky * 3 + kx) * CG * 18;
#pragma unroll 4
                for (int ci = 0; ci < CG; ci++) {
                    float xv = __ldg(xp + ci);
#pragma unroll
                    for (int oc = 0; oc < 18; oc++)
                        acc[oc] += xv * wp[ci * 18 + oc];
                }
            }
        }
    }

    float* op = g_off_buf + ((size_t)g * NPIX + (size_t)(b * HH + y) * WW + px) * 18;
#pragma unroll
    for (int oc = 0; oc < 18; oc++) op[oc] = acc[oc];
}

// ---------------------------------------------------------------------------
// Kernel B: bilinear sampling. One warp per (g, pixel, tap k); lanes = channels.
// Replicates the reference's clip/floor/weight formulas exactly (including the
// degenerate x==W-1 case where all four weights sum to 0).
// ---------------------------------------------------------------------------
__global__ void sample_kernel(const float* __restrict__ x) {
    int wid  = (blockIdx.x * blockDim.x + threadIdx.x) >> 5;
    int lane = threadIdx.x & 31;
    // total warps = GG * NPIX * 9 exactly covers the grid
    int k = wid % 9;
    int t = wid / 9;            // g*NPIX + m
    int m = t & (NPIX - 1);
    int g = t >> 16;            // NPIX = 2^16

    int b    = m >> 14;
    int y    = (m >> 7) & 127;
    int xpix = m & 127;

    const float* offp = g_off_buf + ((size_t)g * NPIX + m) * 18 + 2 * k;
    float ox = offp[0];
    float oy = offp[1];

    float fx = (float)xpix + (float)(k % 3 - 1) + ox;
    float fy = (float)y    + (float)(k / 3 - 1) + oy;
    fx = fminf(fmaxf(fx, 0.f), (float)(WW - 1));
    fy = fminf(fmaxf(fy, 0.f), (float)(HH - 1));

    float x0f = floorf(fx), y0f = floorf(fy);
    float x1f = fminf(x0f + 1.f, (float)(WW - 1));
    float y1f = fminf(y0f + 1.f, (float)(HH - 1));

    float tx  = fx - x0f, ty  = fy - y0f;
    float txc = x1f - fx, tyc = y1f - fy;
    float wa = txc * tyc;   // (y0,x0)
    float wb = txc * ty;    // (y1,x0)
    float wc = tx  * tyc;   // (y0,x1)
    float wd = tx  * ty;    // (y1,x1)

    int x0 = (int)x0f, x1 = (int)x1f, y0 = (int)y0f, y1 = (int)y1f;

    const float* base = x + (size_t)b * HH * WW * CC + g * CG;
    const float* p00 = base + ((size_t)y0 * WW + x0) * CC;
    const float* p10 = base + ((size_t)y1 * WW + x0) * CC;
    const float* p01 = base + ((size_t)y0 * WW + x1) * CC;
    const float* p11 = base + ((size_t)y1 * WW + x1) * CC;

    float* sp = g_samp_buf + ((size_t)g * NPIX + m) * KIN + k * CG;
#pragma unroll
    for (int cc = 0; cc < 2; cc++) {
        int c = lane + cc * 32;
        float v = wa * __ldg(p00 + c) + wb * __ldg(p10 + c)
                + wc * __ldg(p01 + c) + wd * __ldg(p11 + c);
        sp[c] = v;
    }
}

// ---------------------------------------------------------------------------
// Kernel C: fused depthwise(3x3, per-channel) + pointwise GEMM (K=576 -> N=64).
// Per group: M=65536 pixels. Block = 64x64 output tile, BK=16, 4x4 per thread.
// The A tile (depthwise output) is computed on the fly while staging to smem.
// ---------------------------------------------------------------------------
__global__ void dwpw_gemm_kernel(const float* __restrict__ dw_w,
                                 const float* __restrict__ dw_b,
                                 const float* __restrict__ pw_w,
                                 const float* __restrict__ pw_b,
                                 float* __restrict__ out) {
    __shared__ float As[16][65];   // padded: kills 16-way STS conflicts
    __shared__ float Bs[16][64];

    int g  = blockIdx.y;
    int m0 = blockIdx.x * 64;
    int tid = threadIdx.x;         // 256
    int tx = tid & 15;             // 16 col-threads * 4 cols
    int ty = tid >> 4;             // 16 row-threads * 4 rows

    float acc[4][4] = {};

    const int akk  = tid & 15;     // A-load: k within tile
    const int amm0 = tid >> 4;     // A-load: m within tile (base)
    const int bf0  = tid & 63;     // B-load: f
    const int bkk0 = tid >> 6;     // B-load: k base

    for (int kt = 0; kt < 36; kt++) {
        // ---- stage B tile: pw_w[g][kt*16+kk][f] ----
#pragma unroll
        for (int p = 0; p < 4; p++) {
            int kk = bkk0 + p * 4;
            Bs[kk][bf0] = pw_w[((size_t)g * KIN + kt * 16 + kk) * FG + bf0];
        }

        // ---- stage A tile with fused depthwise ----
        {
            int kc = kt * 16 + akk;
            float bias = dw_b[g * KIN + kc];
            // preload the 9 depthwise weights for this channel
            float dwv[9];
#pragma unroll
            for (int j = 0; j < 9; j++)
                dwv[j] = dw_w[((size_t)g * 9 + j) * KIN + kc];

#pragma unroll
            for (int p = 0; p < 4; p++) {
                int mm = amm0 + p * 16;
                int m  = m0 + mm;
                int y  = (m >> 7) & 127;
                int xx = m & 127;
                float a = bias;
#pragma unroll
                for (int j = 0; j < 9; j++) {
                    int ky = j / 3 - 1;
                    int kx = j % 3 - 1;
                    int yy = y + ky;
                    int xq = xx + kx;
                    if (yy >= 0 && yy < HH && xq >= 0 && xq < WW) {
                        a += dwv[j] *
                             g_samp_buf[((size_t)g * NPIX + m + ky * WW + kx) * KIN + kc];
                    }
                }
                As[akk][mm] = a;
            }
        }
        __syncthreads();

        // ---- 64x64x16 inner product ----
#pragma unroll
        for (int kk = 0; kk < 16; kk++) {
            float af[4], bf[4];
#pragma unroll
            for (int i = 0; i < 4; i++) af[i] = As[kk][ty * 4 + i];
#pragma unroll
            for (int jf = 0; jf < 4; jf++) bf[jf] = Bs[kk][tx * 4 + jf];
#pragma unroll
            for (int i = 0; i < 4; i++)
#pragma unroll
                for (int jf = 0; jf < 4; jf++)
                    acc[i][jf] += af[i] * bf[jf];
        }
        __syncthreads();
    }

    // ---- epilogue: bias + write to interleaved output [m, g*64+f] ----
#pragma unroll
    for (int i = 0; i < 4; i++) {
        int m = m0 + ty * 4 + i;
#pragma unroll
        for (int jf = 0; jf < 4; jf++) {
            int f = tx * 4 + jf;
            out[(size_t)m * CC + g * FG + f] = acc[i][jf] + pw_b[g * FG + f];
        }
    }
}

// ---------------------------------------------------------------------------
extern "C" void kernel_launch(void* const* d_in, const int* in_sizes, int n_in,
                              void* d_out, int out_size) {
    (void)in_sizes; (void)n_in; (void)out_size;
    const float* x     = (const float*)d_in[0];
    const float* off_w = (const float*)d_in[1];
    const float* off_b = (const float*)d_in[2];
    const float* dw_w  = (const float*)d_in[3];
    const float* dw_b  = (const float*)d_in[4];
    const float* pw_w  = (const float*)d_in[5];
    const float* pw_b  = (const float*)d_in[6];
    float* out = (float*)d_out;

    // A: offsets
    offset_conv_kernel<<<GG * BB * HH, 128>>>(x, off_w, off_b);

    // B: bilinear sampling; one warp per (g, pixel, tap)
    long long total_threads = (long long)GG * NPIX * 9 * 32;   // 37,748,736
    int blocks = (int)(total_threads / 256);                   // exact: 147456
    sample_kernel<<<blocks, 256>>>(x);

    // C: fused depthwise + pointwise GEMM
    dim3 grid(NPIX / 64, GG);
    dwpw_gemm_kernel<<<grid, 256>>>(dw_w, dw_b, pw_w, pw_b, out);
}